// round 16
// baseline (speedup 1.0000x reference)
#include <cuda_runtime.h>
#include <cuda_fp16.h>
#include <cstdint>

// ===================== problem constants =====================
#define NNF 128
#define NEF 64
#define NGF 64
#define HID 128
#define TGT 64

#define THREADS 512
#define WARPS 16
#define GRID_X 152

// fragment tile counts
#define KT1 24   // 384/16 k-tiles, GEMM1
#define NT1 16   // 128/8  n-tiles, GEMM1
#define KT2 8    // 128/16 k-tiles, GEMM2
#define NT2 8    // 64/8   n-tiles, GEMM2

// ===================== smem offsets (bytes) =====================
#define S_W1  0u        // 24 kt x 8 pairs x 32 lanes x 16B = 98304
#define S_W2  98304u    // 8 kt x 4 pairs x 32 x 16B = 16384
#define S_B1  114688u   // 512
#define S_B2  115200u   // 256
#define S_TOTAL 115456u

// ===================== helpers =====================
__device__ __forceinline__ uint32_t pack2h(float lo, float hi) {
    // f16x2 with 'lo' in low 16 bits (first PTX source -> high half)
    uint32_t r;
    asm("cvt.rn.f16x2.f32 %0, %1, %2;" : "=r"(r) : "f"(hi), "f"(lo));
    return r;
}
// D += A * B  (m16n8k16, fp16 in, f32 accum)
__device__ __forceinline__ void mma_f16(float* c, const uint32_t* a, uint32_t b0, uint32_t b1) {
    asm volatile("mma.sync.aligned.m16n8k16.row.col.f32.f16.f16.f32 "
        "{%0,%1,%2,%3}, {%4,%5,%6,%7}, {%8,%9}, {%0,%1,%2,%3};"
        : "+f"(c[0]), "+f"(c[1]), "+f"(c[2]), "+f"(c[3])
        : "r"(a[0]), "r"(a[1]), "r"(a[2]), "r"(a[3]), "r"(b0), "r"(b1));
}

// ===================== device scratch (pair-interleaved fragments) =====================
__device__ __align__(16) uint2 g_w1[KT1 * NT1 * 32];
__device__ __align__(16) uint2 g_w2[KT2 * NT2 * 32];
__device__ unsigned int g_counter;

// W1 [384,128] ([k][n] row-major) -> per-lane m16n8k16 B fragments (fp16), with a
// K-PERMUTATION inside each 16-k tile: logical k {2q,2q+1,2q+8,2q+9} <- memory
// cols {4q,4q+1,4q+2,4q+3} (q = lane&3):
//   b0 = {W[k0][n], W[k0+1][n]},  b1 = {W[k0+2][n], W[k0+3][n]},  k0 = kt*16 + 4q.
// The A side loads one contiguous float4 (cols 4q..4q+3); .xy -> a0/a1, .zw -> a2/a3.
// Same permutation on both operands => k-sum invariant.
// W2 [128,64] keeps the STANDARD layout (A comes from registers in logical order):
//   b0 = {W[k0][n], W[k0+1][n]}, b1 = {W[k0+8][n], W[k0+9][n]}, k0 = kt*16 + 2q.
// PAIRED storage: uint4 entry ((kt*NP+np)*32+lane) = {frag(nt=2np), frag(nt=2np+1)}.
__global__ void prep_kernel(const float* __restrict__ W1, const float* __restrict__ W2) {
    int idx = blockIdx.x * blockDim.x + threadIdx.x;
    if (idx == 0) g_counter = 0u;
    const int total1 = KT1 * NT1 * 32;
    if (idx < total1) {
        int lane = idx & 31, tile = idx >> 5;
        int nt = tile % NT1, kt = tile / NT1;
        int k0 = kt * 16 + (lane & 3) * 4;        // permuted: 4 consecutive rows
        int n  = nt * 8 + (lane >> 2);
        float w00 = W1[(size_t)k0 * HID + n];
        float w01 = W1[(size_t)(k0 + 1) * HID + n];
        float w10 = W1[(size_t)(k0 + 2) * HID + n];
        float w11 = W1[(size_t)(k0 + 3) * HID + n];
        size_t dst = (size_t)2 * (((size_t)kt * 8 + (nt >> 1)) * 32 + lane) + (nt & 1);
        g_w1[dst] = make_uint2(pack2h(w00, w01), pack2h(w10, w11));
    } else if (idx < total1 + KT2 * NT2 * 32) {
        int j = idx - total1;
        int lane = j & 31, tile = j >> 5;
        int nt = tile % NT2, kt = tile / NT2;
        int k0 = kt * 16 + (lane & 3) * 2;        // standard layout for W2
        int n  = nt * 8 + (lane >> 2);
        float w00 = W2[(size_t)k0 * TGT + n];
        float w01 = W2[(size_t)(k0 + 1) * TGT + n];
        float w10 = W2[(size_t)(k0 + 8) * TGT + n];
        float w11 = W2[(size_t)(k0 + 9) * TGT + n];
        size_t dst = (size_t)2 * (((size_t)kt * 4 + (nt >> 1)) * 32 + lane) + (nt & 1);
        g_w2[dst] = make_uint2(pack2h(w00, w01), pack2h(w10, w11));
    }
}

// ===================== main fused kernel =====================
extern "C" __global__ void __launch_bounds__(THREADS, 1)
edge_mlp(const float* __restrict__ ek, const float* __restrict__ vrk,
         const float* __restrict__ vsk, const float* __restrict__ u,
         const int* __restrict__ batch,
         const float* __restrict__ b1, const float* __restrict__ b2,
         float* __restrict__ out, int ngroups) {
    extern __shared__ __align__(16) unsigned char smem[];
    const int tid = threadIdx.x;

    // -------- prologue: weight fragments + biases to smem --------
    {
        uint4* d = (uint4*)(smem + S_W1);
        const uint4* s = (const uint4*)g_w1;
        for (int i = tid; i < 98304 / 16; i += THREADS) d[i] = s[i];
        d = (uint4*)(smem + S_W2); s = (const uint4*)g_w2;
        for (int i = tid; i < 16384 / 16; i += THREADS) d[i] = s[i];
        float* b1s = (float*)(smem + S_B1);
        float* b2s = (float*)(smem + S_B2);
        if (tid < HID) b1s[tid] = b1[tid];
        if (tid < TGT) b2s[tid] = b2[tid];
    }
    __syncthreads();

    const uint4* w1p = (const uint4*)(smem + S_W1);
    const uint4* w2p = (const uint4*)(smem + S_W2);
    const float* b1s = (const float*)(smem + S_B1);
    const float* b2s = (const float*)(smem + S_B2);

    const int lane = tid & 31;
    const int qrow  = lane >> 2;        // 0..7
    const int qcol  = (lane & 3) * 2;   // 0,2,4,6 (bias / output indexing)
    const int qcol4 = (lane & 3) * 4;   // 0,4,8,12 (coalesced x load, permuted K)

    // dynamic work stealing (group = 16 edge rows)
    unsigned int cur = 0xFFFFFFFFu;
    if (lane == 0) cur = atomicAdd(&g_counter, 1u);
    cur = __shfl_sync(0xFFFFFFFFu, cur, 0);

    while (cur < (unsigned)ngroups) {
        unsigned int nxt = 0xFFFFFFFFu;
        if (lane == 0) nxt = atomicAdd(&g_counter, 1u);   // issued early, latency hidden

        const int r0 = (int)cur * 16 + qrow;
        const int r1 = r0 + 8;
        const int gb0 = batch[r0];
        const int gb1 = batch[r1];

        float acc[64];   // GEMM1 C: 16 n-tiles x 4
        #pragma unroll
        for (int i = 0; i < 64; ++i) acc[i] = 0.f;

        // ================= GEMM1: K = 384, unroll-2, distance-2 prefetch, =================
        // =================      incremental pointers (even=pA, odd=pB)      =================
        const float* pA0 = ek + (size_t)r0 * NEF + qcol4;   // even tiles (kt=0,2,..)
        const float* pA1 = ek + (size_t)r1 * NEF + qcol4;
        const float* pB0 = pA0 + 16;                        // odd tiles (kt=1,3,..)
        const float* pB1 = pA1 + 16;
        float4 vA0 = *(const float4*)pA0, vA1 = *(const float4*)pA1;
        float4 vB0 = *(const float4*)pB0, vB1 = *(const float4*)pB1;

        #pragma unroll 1
        for (int kt = 0; kt < KT1; kt += 2) {
            // ---- even tile kt: consume vA (loaded 2 bodies ago), refill for kt+2 ----
            {
                uint32_t a[4];
                a[0] = pack2h(vA0.x, vA0.y);
                a[1] = pack2h(vA1.x, vA1.y);
                a[2] = pack2h(vA0.z, vA0.w);
                a[3] = pack2h(vA1.z, vA1.w);
                if (kt < KT1 - 2) {
                    if (kt == 2)       { pA0 = vrk + (size_t)r0 * NNF + qcol4; pA1 = vrk + (size_t)r1 * NNF + qcol4; }
                    else if (kt == 10) { pA0 = vsk + (size_t)r0 * NNF + qcol4; pA1 = vsk + (size_t)r1 * NNF + qcol4; }
                    else if (kt == 18) { pA0 = u + (size_t)gb0 * NGF + qcol4;  pA1 = u + (size_t)gb1 * NGF + qcol4; }
                    else               { pA0 += 32; pA1 += 32; }
                    vA0 = *(const float4*)pA0;
                    vA1 = *(const float4*)pA1;
                }
                const uint4* bw = w1p + (size_t)kt * 8 * 32 + lane;
                #pragma unroll
                for (int np = 0; np < 8; ++np) {
                    const uint4 f = bw[np * 32];
                    mma_f16(acc + (np * 2) * 4,     a, f.x, f.y);
                    mma_f16(acc + (np * 2 + 1) * 4, a, f.z, f.w);
                }
            }
            // ---- odd tile kt+1: consume vB, refill for kt+3 ----
            {
                uint32_t a[4];
                a[0] = pack2h(vB0.x, vB0.y);
                a[1] = pack2h(vB1.x, vB1.y);
                a[2] = pack2h(vB0.z, vB0.w);
                a[3] = pack2h(vB1.z, vB1.w);
                if (kt < KT1 - 2) {
                    if (kt == 2)       { pB0 = vrk + (size_t)r0 * NNF + 16 + qcol4; pB1 = vrk + (size_t)r1 * NNF + 16 + qcol4; }
                    else if (kt == 10) { pB0 = vsk + (size_t)r0 * NNF + 16 + qcol4; pB1 = vsk + (size_t)r1 * NNF + 16 + qcol4; }
                    else if (kt == 18) { pB0 = u + (size_t)gb0 * NGF + 16 + qcol4;  pB1 = u + (size_t)gb1 * NGF + 16 + qcol4; }
                    else               { pB0 += 32; pB1 += 32; }
                    vB0 = *(const float4*)pB0;
                    vB1 = *(const float4*)pB1;
                }
                const uint4* bw = w1p + (size_t)(kt + 1) * 8 * 32 + lane;
                #pragma unroll
                for (int np = 0; np < 8; ++np) {
                    const uint4 f = bw[np * 32];
                    mma_f16(acc + (np * 2) * 4,     a, f.x, f.y);
                    mma_f16(acc + (np * 2 + 1) * 4, a, f.z, f.w);
                }
            }
        }

        // ================= bias + ReLU =================
        #pragma unroll
        for (int nt = 0; nt < NT1; ++nt) {
            const float2 bb = *(const float2*)(b1s + nt * 8 + qcol);
            acc[nt * 4 + 0] = fmaxf(acc[nt * 4 + 0] + bb.x, 0.f);
            acc[nt * 4 + 1] = fmaxf(acc[nt * 4 + 1] + bb.y, 0.f);
            acc[nt * 4 + 2] = fmaxf(acc[nt * 4 + 2] + bb.x, 0.f);
            acc[nt * 4 + 3] = fmaxf(acc[nt * 4 + 3] + bb.y, 0.f);
        }

        // ================= GEMM2: h [16x128] @ W2 [128x64], register A (standard layout) =================
        float c2[32];
        #pragma unroll
        for (int i = 0; i < 32; ++i) c2[i] = 0.f;

        #pragma unroll
        for (int kt = 0; kt < KT2; ++kt) {
            // C1 fragment (n-tiles 2kt,2kt+1) == A2 fragment for k-cols 16kt..16kt+15
            const float* s0 = acc + kt * 8;
            uint32_t a[4];
            a[0] = pack2h(s0[0], s0[1]); a[1] = pack2h(s0[2], s0[3]);
            a[2] = pack2h(s0[4], s0[5]); a[3] = pack2h(s0[6], s0[7]);

            const uint4* bw = w2p + (size_t)kt * 4 * 32 + lane;
            #pragma unroll
            for (int np = 0; np < 4; ++np) {
                const uint4 f = bw[np * 32];
                mma_f16(c2 + (np * 2) * 4,     a, f.x, f.y);
                mma_f16(c2 + (np * 2 + 1) * 4, a, f.z, f.w);
            }
        }

        // ================= epilogue: + b2, store fp32 =================
        #pragma unroll
        for (int nt = 0; nt < NT2; ++nt) {
            const float2 bb = *(const float2*)(b2s + nt * 8 + qcol);
            float2 o0, o1;
            o0.x = c2[nt * 4 + 0] + bb.x;
            o0.y = c2[nt * 4 + 1] + bb.y;
            o1.x = c2[nt * 4 + 2] + bb.x;
            o1.y = c2[nt * 4 + 3] + bb.y;
            *(float2*)(out + (size_t)r0 * TGT + nt * 8 + qcol) = o0;
            *(float2*)(out + (size_t)r1 * TGT + nt * 8 + qcol) = o1;
        }

        cur = __shfl_sync(0xFFFFFFFFu, nxt, 0);
    }
}

// ===================== launch =====================
extern "C" void kernel_launch(void* const* d_in, const int* in_sizes, int n_in,
                              void* d_out, int out_size) {
    (void)n_in; (void)out_size;
    const float* ek  = (const float*)d_in[0];
    const float* vrk = (const float*)d_in[1];
    const float* vsk = (const float*)d_in[2];
    const float* u   = (const float*)d_in[3];
    const int*   batch = (const int*)d_in[4];
    const float* W1  = (const float*)d_in[5];
    const float* b1  = (const float*)d_in[6];
    const float* W2  = (const float*)d_in[7];
    const float* b2  = (const float*)d_in[8];
    float* out = (float*)d_out;

    const int E = in_sizes[0] / NEF;
    const int ngroups = E / 16;

    const int prep_total = KT1 * NT1 * 32 + KT2 * NT2 * 32;
    prep_kernel<<<(prep_total + 255) / 256, 256>>>(W1, W2);

    cudaFuncSetAttribute(edge_mlp, cudaFuncAttributeMaxDynamicSharedMemorySize, S_TOTAL);
    edge_mlp<<<GRID_X, THREADS, S_TOTAL>>>(ek, vrk, vsk, u, batch, b1, b2, out, ngroups);
}

// round 17
// speedup vs baseline: 1.4186x; 1.4186x over previous
#include <cuda_runtime.h>
#include <cuda_fp16.h>
#include <cstdint>

// ===================== problem constants =====================
#define NNF 128
#define NEF 64
#define NGF 64
#define HID 128
#define TGT 64

#define THREADS 480
#define WARPS 15
#define GRID_X 152

// fragment tile counts
#define KT1 24   // 384/16 k-tiles, GEMM1
#define NT1 16   // 128/8  n-tiles, GEMM1
#define KT2 8    // 128/16 k-tiles, GEMM2
#define NT2 8    // 64/8   n-tiles, GEMM2

// ===================== smem offsets (bytes) =====================
#define S_W1  0u        // 24 kt x 8 pairs x 32 lanes x 16B = 98304
#define S_W2  98304u    // 8 kt x 4 pairs x 32 x 16B = 16384
#define S_B1  114688u   // 512
#define S_B2  115200u   // 256
#define S_TOTAL 115456u

// ===================== helpers =====================
__device__ __forceinline__ uint32_t pack2h(float lo, float hi) {
    // f16x2 with 'lo' in low 16 bits (first PTX source -> high half)
    uint32_t r;
    asm("cvt.rn.f16x2.f32 %0, %1, %2;" : "=r"(r) : "f"(hi), "f"(lo));
    return r;
}
// D += A * B  (m16n8k16, fp16 in, f32 accum)
__device__ __forceinline__ void mma_f16(float* c, const uint32_t* a, uint32_t b0, uint32_t b1) {
    asm volatile("mma.sync.aligned.m16n8k16.row.col.f32.f16.f16.f32 "
        "{%0,%1,%2,%3}, {%4,%5,%6,%7}, {%8,%9}, {%0,%1,%2,%3};"
        : "+f"(c[0]), "+f"(c[1]), "+f"(c[2]), "+f"(c[3])
        : "r"(a[0]), "r"(a[1]), "r"(a[2]), "r"(a[3]), "r"(b0), "r"(b1));
}

// ===================== device scratch (pair-interleaved fragments) =====================
__device__ __align__(16) uint2 g_w1[KT1 * NT1 * 32];
__device__ __align__(16) uint2 g_w2[KT2 * NT2 * 32];
__device__ unsigned int g_counter;

// W1 [384,128] ([k][n] row-major) -> per-lane m16n8k16 B fragments (fp16), with a
// K-PERMUTATION inside each 16-k tile: logical k {2q,2q+1,2q+8,2q+9} <- memory
// cols {4q,4q+1,4q+2,4q+3} (q = lane&3):
//   b0 = {W[k0][n], W[k0+1][n]},  b1 = {W[k0+2][n], W[k0+3][n]},  k0 = kt*16 + 4q.
// The A side loads one contiguous float4 (cols 4q..4q+3); .xy -> a0/a1, .zw -> a2/a3.
// Same permutation on both operands => k-sum invariant.
// W2 [128,64] keeps the STANDARD layout (A comes from registers in logical order):
//   b0 = {W[k0][n], W[k0+1][n]}, b1 = {W[k0+8][n], W[k0+9][n]}, k0 = kt*16 + 2q.
// PAIRED storage: uint4 entry ((kt*NP+np)*32+lane) = {frag(nt=2np), frag(nt=2np+1)}.
__global__ void prep_kernel(const float* __restrict__ W1, const float* __restrict__ W2) {
    int idx = blockIdx.x * blockDim.x + threadIdx.x;
    if (idx == 0) g_counter = 0u;
    const int total1 = KT1 * NT1 * 32;
    if (idx < total1) {
        int lane = idx & 31, tile = idx >> 5;
        int nt = tile % NT1, kt = tile / NT1;
        int k0 = kt * 16 + (lane & 3) * 4;        // permuted: 4 consecutive rows
        int n  = nt * 8 + (lane >> 2);
        float w00 = W1[(size_t)k0 * HID + n];
        float w01 = W1[(size_t)(k0 + 1) * HID + n];
        float w10 = W1[(size_t)(k0 + 2) * HID + n];
        float w11 = W1[(size_t)(k0 + 3) * HID + n];
        size_t dst = (size_t)2 * (((size_t)kt * 8 + (nt >> 1)) * 32 + lane) + (nt & 1);
        g_w1[dst] = make_uint2(pack2h(w00, w01), pack2h(w10, w11));
    } else if (idx < total1 + KT2 * NT2 * 32) {
        int j = idx - total1;
        int lane = j & 31, tile = j >> 5;
        int nt = tile % NT2, kt = tile / NT2;
        int k0 = kt * 16 + (lane & 3) * 2;        // standard layout for W2
        int n  = nt * 8 + (lane >> 2);
        float w00 = W2[(size_t)k0 * TGT + n];
        float w01 = W2[(size_t)(k0 + 1) * TGT + n];
        float w10 = W2[(size_t)(k0 + 8) * TGT + n];
        float w11 = W2[(size_t)(k0 + 9) * TGT + n];
        size_t dst = (size_t)2 * (((size_t)kt * 4 + (nt >> 1)) * 32 + lane) + (nt & 1);
        g_w2[dst] = make_uint2(pack2h(w00, w01), pack2h(w10, w11));
    }
}

// ===================== main fused kernel =====================
extern "C" __global__ void __launch_bounds__(THREADS, 1)
edge_mlp(const float* __restrict__ ek, const float* __restrict__ vrk,
         const float* __restrict__ vsk, const float* __restrict__ u,
         const int* __restrict__ batch,
         const float* __restrict__ b1, const float* __restrict__ b2,
         float* __restrict__ out, int ngroups) {
    extern __shared__ __align__(16) unsigned char smem[];
    const int tid = threadIdx.x;

    // -------- prologue: weight fragments + biases to smem --------
    {
        uint4* d = (uint4*)(smem + S_W1);
        const uint4* s = (const uint4*)g_w1;
        for (int i = tid; i < 98304 / 16; i += THREADS) d[i] = s[i];
        d = (uint4*)(smem + S_W2); s = (const uint4*)g_w2;
        for (int i = tid; i < 16384 / 16; i += THREADS) d[i] = s[i];
        float* b1s = (float*)(smem + S_B1);
        float* b2s = (float*)(smem + S_B2);
        if (tid < HID) b1s[tid] = b1[tid];
        if (tid < TGT) b2s[tid] = b2[tid];
    }
    __syncthreads();

    const uint4* w1p = (const uint4*)(smem + S_W1);
    const uint4* w2p = (const uint4*)(smem + S_W2);
    const float* b1s = (const float*)(smem + S_B1);
    const float* b2s = (const float*)(smem + S_B2);

    const int lane = tid & 31;
    const int qrow  = lane >> 2;        // 0..7
    const int qcol  = (lane & 3) * 2;   // 0,2,4,6 (bias / output indexing)
    const int qcol4 = (lane & 3) * 4;   // 0,4,8,12 (coalesced x load, permuted K)

    // dynamic work stealing (group = 16 edge rows)
    unsigned int cur = 0xFFFFFFFFu;
    if (lane == 0) cur = atomicAdd(&g_counter, 1u);
    cur = __shfl_sync(0xFFFFFFFFu, cur, 0);

    while (cur < (unsigned)ngroups) {
        unsigned int nxt = 0xFFFFFFFFu;
        if (lane == 0) nxt = atomicAdd(&g_counter, 1u);   // issued early, latency hidden

        const int r0 = (int)cur * 16 + qrow;
        const int r1 = r0 + 8;
        const int gb0 = batch[r0];
        const int gb1 = batch[r1];

        float acc[64];   // GEMM1 C: 16 n-tiles x 4
        #pragma unroll
        for (int i = 0; i < 64; ++i) acc[i] = 0.f;

        // ================= GEMM1: K = 384, unroll-2, distance-2 prefetch, =================
        // =================   incremental pointers (even=pA, odd=pB)        =================
        const float* pA0 = ek + (size_t)r0 * NEF + qcol4;   // even tiles (kt=0,2,..)
        const float* pA1 = ek + (size_t)r1 * NEF + qcol4;
        const float* pB0 = pA0 + 16;                        // odd tiles (kt=1,3,..)
        const float* pB1 = pA1 + 16;
        float4 vA0 = *(const float4*)pA0, vA1 = *(const float4*)pA1;
        float4 vB0 = *(const float4*)pB0, vB1 = *(const float4*)pB1;

        #pragma unroll 1
        for (int kt = 0; kt < KT1; kt += 2) {
            // ---- even tile kt: consume vA (loaded 2 bodies ago), refill for kt+2 ----
            {
                uint32_t a[4];
                a[0] = pack2h(vA0.x, vA0.y);
                a[1] = pack2h(vA1.x, vA1.y);
                a[2] = pack2h(vA0.z, vA0.w);
                a[3] = pack2h(vA1.z, vA1.w);
                if (kt < KT1 - 2) {
                    if (kt == 2)       { pA0 = vrk + (size_t)r0 * NNF + qcol4; pA1 = vrk + (size_t)r1 * NNF + qcol4; }
                    else if (kt == 10) { pA0 = vsk + (size_t)r0 * NNF + qcol4; pA1 = vsk + (size_t)r1 * NNF + qcol4; }
                    else if (kt == 18) { pA0 = u + (size_t)gb0 * NGF + qcol4;  pA1 = u + (size_t)gb1 * NGF + qcol4; }
                    else               { pA0 += 32; pA1 += 32; }
                    vA0 = *(const float4*)pA0;
                    vA1 = *(const float4*)pA1;
                }
                const uint4* bw = w1p + (size_t)kt * 8 * 32 + lane;
                #pragma unroll
                for (int np = 0; np < 8; ++np) {
                    const uint4 f = bw[np * 32];
                    mma_f16(acc + (np * 2) * 4,     a, f.x, f.y);
                    mma_f16(acc + (np * 2 + 1) * 4, a, f.z, f.w);
                }
            }
            // ---- odd tile kt+1: consume vB, refill for kt+3 ----
            {
                uint32_t a[4];
                a[0] = pack2h(vB0.x, vB0.y);
                a[1] = pack2h(vB1.x, vB1.y);
                a[2] = pack2h(vB0.z, vB0.w);
                a[3] = pack2h(vB1.z, vB1.w);
                if (kt < KT1 - 2) {
                    if (kt == 2)       { pB0 = vrk + (size_t)r0 * NNF + 16 + qcol4; pB1 = vrk + (size_t)r1 * NNF + 16 + qcol4; }
                    else if (kt == 10) { pB0 = vsk + (size_t)r0 * NNF + 16 + qcol4; pB1 = vsk + (size_t)r1 * NNF + 16 + qcol4; }
                    else if (kt == 18) { pB0 = u + (size_t)gb0 * NGF + 16 + qcol4;  pB1 = u + (size_t)gb1 * NGF + 16 + qcol4; }
                    else               { pB0 += 32; pB1 += 32; }
                    vB0 = *(const float4*)pB0;
                    vB1 = *(const float4*)pB1;
                }
                const uint4* bw = w1p + (size_t)(kt + 1) * 8 * 32 + lane;
                #pragma unroll
                for (int np = 0; np < 8; ++np) {
                    const uint4 f = bw[np * 32];
                    mma_f16(acc + (np * 2) * 4,     a, f.x, f.y);
                    mma_f16(acc + (np * 2 + 1) * 4, a, f.z, f.w);
                }
            }
        }

        // ================= bias + ReLU =================
        #pragma unroll
        for (int nt = 0; nt < NT1; ++nt) {
            const float2 bb = *(const float2*)(b1s + nt * 8 + qcol);
            acc[nt * 4 + 0] = fmaxf(acc[nt * 4 + 0] + bb.x, 0.f);
            acc[nt * 4 + 1] = fmaxf(acc[nt * 4 + 1] + bb.y, 0.f);
            acc[nt * 4 + 2] = fmaxf(acc[nt * 4 + 2] + bb.x, 0.f);
            acc[nt * 4 + 3] = fmaxf(acc[nt * 4 + 3] + bb.y, 0.f);
        }

        // ================= GEMM2: h [16x128] @ W2 [128x64], register A (standard layout) =================
        float c2[32];
        #pragma unroll
        for (int i = 0; i < 32; ++i) c2[i] = 0.f;

        #pragma unroll
        for (int kt = 0; kt < KT2; ++kt) {
            // C1 fragment (n-tiles 2kt,2kt+1) == A2 fragment for k-cols 16kt..16kt+15
            const float* s0 = acc + kt * 8;
            uint32_t a[4];
            a[0] = pack2h(s0[0], s0[1]); a[1] = pack2h(s0[2], s0[3]);
            a[2] = pack2h(s0[4], s0[5]); a[3] = pack2h(s0[6], s0[7]);

            const uint4* bw = w2p + (size_t)kt * 4 * 32 + lane;
            #pragma unroll
            for (int np = 0; np < 4; ++np) {
                const uint4 f = bw[np * 32];
                mma_f16(c2 + (np * 2) * 4,     a, f.x, f.y);
                mma_f16(c2 + (np * 2 + 1) * 4, a, f.z, f.w);
            }
        }

        // ================= epilogue: + b2, store fp32 =================
        #pragma unroll
        for (int nt = 0; nt < NT2; ++nt) {
            const float2 bb = *(const float2*)(b2s + nt * 8 + qcol);
            float2 o0, o1;
            o0.x = c2[nt * 4 + 0] + bb.x;
            o0.y = c2[nt * 4 + 1] + bb.y;
            o1.x = c2[nt * 4 + 2] + bb.x;
            o1.y = c2[nt * 4 + 3] + bb.y;
            *(float2*)(out + (size_t)r0 * TGT + nt * 8 + qcol) = o0;
            *(float2*)(out + (size_t)r1 * TGT + nt * 8 + qcol) = o1;
        }

        cur = __shfl_sync(0xFFFFFFFFu, nxt, 0);
    }
}

// ===================== launch =====================
extern "C" void kernel_launch(void* const* d_in, const int* in_sizes, int n_in,
                              void* d_out, int out_size) {
    (void)n_in; (void)out_size;
    const float* ek  = (const float*)d_in[0];
    const float* vrk = (const float*)d_in[1];
    const float* vsk = (const float*)d_in[2];
    const float* u   = (const float*)d_in[3];
    const int*   batch = (const int*)d_in[4];
    const float* W1  = (const float*)d_in[5];
    const float* b1  = (const float*)d_in[6];
    const float* W2  = (const float*)d_in[7];
    const float* b2  = (const float*)d_in[8];
    float* out = (float*)d_out;

    const int E = in_sizes[0] / NEF;
    const int ngroups = E / 16;

    const int prep_total = KT1 * NT1 * 32 + KT2 * NT2 * 32;
    prep_kernel<<<(prep_total + 255) / 256, 256>>>(W1, W2);

    cudaFuncSetAttribute(edge_mlp, cudaFuncAttributeMaxDynamicSharedMemorySize, S_TOTAL);
    edge_mlp<<<GRID_X, THREADS, S_TOTAL>>>(ek, vrk, vsk, u, batch, b1, b2, out, ngroups);
}